// round 12
// baseline (speedup 1.0000x reference)
#include <cuda_runtime.h>

// KREmbedding: Gaussian-weighted context embedding aggregation.
// context: [B, C] int32, center: [B] int32, W: [V, D] float32 -> out [B, D] float32
// B=8192, C=32, D=512, SIGMA=1.0
//
// Round 12: 4 warps per batch row (8 context rows each).
//   Bound (unchanged): expf(-d2/2)==0.0f exactly when d2>~208 (fp32
//   underflow); per-row 160-element partial (float4 + scalar per lane),
//   fixed-point floor(min(p,60000)*1024), one redux.sync.add.s32 ->
//   warp-uniform S <= 1024*d2; S > 220*1024 proves w==0.0f in the fp32
//   reference too (survival ~0.3%). 8 rows per warp in one flat pipelined
//   loop, single min-folded survivor branch, cold __noinline__ exact path.
//   Halved per-warp critical path + 2x warp count (32768 warps) attacks the
//   remaining latency-boundness; regs ~40 -> 12 blocks/SM (75% theor. occ).
//   Lazy accumulator: slices zeroed only on first survivor; no-survivor
//   blocks (~80%) store exact zeros directly.

#define KB_B 8192
#define KB_C 32
#define KB_D 512
#define NTHREADS 128            // 4 warps, all on one batch row
#define ROWS_PER_WARP 8
#define T_INT (220 * 1024)
#define ROW_BYTES (KB_D * 4)    // 2048; idx*2048 fits in 32 bits (V=50000)

__device__ __forceinline__ float warp_sum(float v) {
#pragma unroll
    for (int off = 16; off; off >>= 1)
        v += __shfl_xor_sync(0xffffffffu, v, off);
    return v;
}

__device__ __forceinline__ float quarter_d2(float4 r, float4 c) {
    float dx = r.x - c.x, dy = r.y - c.y, dz = r.z - c.z, dw = r.w - c.w;
    float d = dx * dx;
    d = fmaf(dy, dy, d);
    d = fmaf(dz, dz, d);
    d = fmaf(dw, dw, d);
    return d;
}

__device__ __forceinline__ int bound_int(float p) {
    return __float2int_rd(fminf(p, 60000.f) * 1024.f);   // floor -> lower bound
}

// Cold path: warp-uniform entry, ~0.3% of rows. Exact full fp32 distance from
// L1-hot data, then exp + accumulate. 256-element REDUX bound prunes first.
// Lazily zeroes this warp's acc slice on first actual accumulation.
__device__ __noinline__ float slow_path(const float4* __restrict__ rowp,
                                        const float4* __restrict__ cenp,
                                        float4 cen0, int lane,
                                        float4* __restrict__ sacc,
                                        int* __restrict__ flag)
{
    const float4 r1   = __ldg(&rowp[lane + 32]);
    const float4 cen1 = __ldg(&cenp[lane + 32]);
    const float4 r0   = __ldg(&rowp[lane]);
    const float pa  = quarter_d2(r0, cen0) + quarter_d2(r1, cen1);
    const int s2 = __reduce_add_sync(0xffffffffu, bound_int(pa));
    if (s2 > T_INT) return 0.f;                    // provably w == 0.0f

    // lazy init (warp-uniform path; this warp is the only writer of its slice)
    if (*flag == 0) {
#pragma unroll
        for (int i = 0; i < 4; i++)
            sacc[lane + 32 * i] = make_float4(0.f, 0.f, 0.f, 0.f);
        __syncwarp();
        if (lane == 0) *flag = 1;
    }

    const float4 cen2 = __ldg(&cenp[lane + 64]);
    const float4 cen3 = __ldg(&cenp[lane + 96]);
    const float4 r2   = __ldg(&rowp[lane + 64]);
    const float4 r3   = __ldg(&rowp[lane + 96]);
    const float t  = warp_sum(pa);
    const float d2 = t + warp_sum(quarter_d2(r2, cen2) + quarter_d2(r3, cen3));

    const float e = __expf(-0.5f * d2);

    float4 a;
    a = sacc[lane];
    a.x = fmaf(e, r0.x, a.x); a.y = fmaf(e, r0.y, a.y);
    a.z = fmaf(e, r0.z, a.z); a.w = fmaf(e, r0.w, a.w);
    sacc[lane] = a;
    a = sacc[lane + 32];
    a.x = fmaf(e, r1.x, a.x); a.y = fmaf(e, r1.y, a.y);
    a.z = fmaf(e, r1.z, a.z); a.w = fmaf(e, r1.w, a.w);
    sacc[lane + 32] = a;
    a = sacc[lane + 64];
    a.x = fmaf(e, r2.x, a.x); a.y = fmaf(e, r2.y, a.y);
    a.z = fmaf(e, r2.z, a.z); a.w = fmaf(e, r2.w, a.w);
    sacc[lane + 64] = a;
    a = sacc[lane + 96];
    a.x = fmaf(e, r3.x, a.x); a.y = fmaf(e, r3.y, a.y);
    a.z = fmaf(e, r3.z, a.z); a.w = fmaf(e, r3.w, a.w);
    sacc[lane + 96] = a;
    return e;
}

__global__ __launch_bounds__(NTHREADS, 12)
void kre_kernel(const int* __restrict__ context,
                const int* __restrict__ center,
                const float* __restrict__ W,
                float* __restrict__ out)
{
    const int tid  = threadIdx.x;
    const int lane = tid & 31;
    const int wid  = tid >> 5;
    const int b    = blockIdx.x;                   // one batch row per block

    __shared__ float4 s_acc[4][KB_D / 4];          // per-warp slices (8 KB)
    __shared__ float  s_esum[4];
    __shared__ int    s_flag[4];
    float4* sacc = s_acc[wid];
    if (lane == 0) s_flag[wid] = 0;

    // warp wid owns context rows [wid*8, wid*8+8); indices in lanes 0..7 (replicated)
    const int my_idx  = __ldg(&context[b * KB_C + wid * ROWS_PER_WARP + (lane & 7)]);
    const int cen_idx = __ldg(&center[b]);
    const char* Wb = reinterpret_cast<const char*>(W);
    const char* cenb = Wb + (unsigned)cen_idx * ROW_BYTES;
    const float4* cenp = reinterpret_cast<const float4*>(cenb);
    const float4  cen0 = __ldg(&cenp[lane]);
    const float   cen4 = __ldg(reinterpret_cast<const float*>(cenb) + 128 + lane);

    float esum = 0.f;

    // ---- flat 8-row pipelined bound pass ----
    int s[ROWS_PER_WARP];
#pragma unroll
    for (int k = 0; k < ROWS_PER_WARP; k++) {
        const int idx = __shfl_sync(0xffffffffu, my_idx, k);
        const char* rowb = Wb + (unsigned)idx * ROW_BYTES;
        const float4 r  = __ldg(reinterpret_cast<const float4*>(rowb) + lane);
        const float  r4 = __ldg(reinterpret_cast<const float*>(rowb) + 128 + lane);
        const float  dx = r4 - cen4;
        const float  p  = fmaf(dx, dx, quarter_d2(r, cen0));    // 160-elem partial
        s[k] = __reduce_add_sync(0xffffffffu, bound_int(p));
    }

    // min-fold: one branch for all 8 rows in the common case
    int smin = s[0];
#pragma unroll
    for (int k = 1; k < ROWS_PER_WARP; k++) smin = min(smin, s[k]);

    if (smin <= T_INT) {                            // rare (~2.5% of warps)
#pragma unroll
        for (int k = 0; k < ROWS_PER_WARP; k++) {
            if (s[k] <= T_INT) {
                const int idx = __shfl_sync(0xffffffffu, my_idx, k);
                const float4* rowp =
                    reinterpret_cast<const float4*>(Wb + (unsigned)idx * ROW_BYTES);
                esum += slow_path(rowp, cenp, cen0, lane, sacc, &s_flag[wid]);
            }
        }
    }

    if (lane == 0) s_esum[wid] = esum;
    __syncthreads();

    // block epilogue: combine 4 warp slices; 128 threads x 1 float4 = 512 floats
    const int f0 = s_flag[0], f1 = s_flag[1], f2 = s_flag[2], f3 = s_flag[3];
    float4* op = reinterpret_cast<float4*>(out + (size_t)b * KB_D);

    if ((f0 | f1 | f2 | f3) == 0) {
        // common case (~80% of blocks): no survivors -> output exactly 0
        __stcs(&op[tid], make_float4(0.f, 0.f, 0.f, 0.f));
    } else {
        const float inv = 1.0f / (s_esum[0] + s_esum[1] + s_esum[2] + s_esum[3] + 1e-8f);
        float4 v = make_float4(0.f, 0.f, 0.f, 0.f);
        if (f0) {
            const float4 a = s_acc[0][tid];
            v.x += a.x; v.y += a.y; v.z += a.z; v.w += a.w;
        }
        if (f1) {
            const float4 a = s_acc[1][tid];
            v.x += a.x; v.y += a.y; v.z += a.z; v.w += a.w;
        }
        if (f2) {
            const float4 a = s_acc[2][tid];
            v.x += a.x; v.y += a.y; v.z += a.z; v.w += a.w;
        }
        if (f3) {
            const float4 a = s_acc[3][tid];
            v.x += a.x; v.y += a.y; v.z += a.z; v.w += a.w;
        }
        v.x *= inv; v.y *= inv; v.z *= inv; v.w *= inv;
        __stcs(&op[tid], v);
    }
}

extern "C" void kernel_launch(void* const* d_in, const int* in_sizes, int n_in,
                              void* d_out, int out_size)
{
    const int* context = (const int*)d_in[0];
    const int* center  = (const int*)d_in[1];
    const float* W     = (const float*)d_in[2];
    for (int i = 0; i < n_in; i++) {
        if (in_sizes[i] == KB_B * KB_C)      context = (const int*)d_in[i];
        else if (in_sizes[i] == KB_B)        center  = (const int*)d_in[i];
        else if (in_sizes[i] > KB_B * KB_C)  W       = (const float*)d_in[i];
    }
    float* out = (float*)d_out;
    kre_kernel<<<KB_B, NTHREADS>>>(context, center, W, out);
}

// round 13
// speedup vs baseline: 1.0947x; 1.0947x over previous
#include <cuda_runtime.h>

// KREmbedding: Gaussian-weighted context embedding aggregation.
// context: [B, C] int32, center: [B] int32, W: [V, D] float32 -> out [B, D] float32
// B=8192, C=32, D=512, SIGMA=1.0
//
// Round 13: quad-row group reduction (no REDUX, no fixed point).
//   Skip proof: expf(-d2/2)==0.0f exactly when d2>~208 (fp32 underflow).
//   A warp evaluates 4 rows at once: lane groups of 8 (g=lane>>3) each own
//   row 4q+g; each lane covers 20 elems (5 float4 at (lane&7)+8j, elems
//   0..159). One 3-level xor-shfl tree (masks 4,2,1, confined to each group)
//   reduces ALL 4 rows simultaneously -> per-group 160-elem partial, bitwise
//   identical within the group. fp32 sum rel-err <=~1e-5 vs the 220-vs-208
//   threshold margin (5.7%) keeps the bound provable: partial > 220 =>
//   reference d2 > 219.9 > 208 => w == 0.0f exactly. Dispatch via one
//   __ballot_sync per quad (warp-uniform). Survivors (~0.3%) take the cold
//   exact path. Lazy accumulator + zero-store epilogue as R11.

#define KB_B 8192
#define KB_C 32
#define KB_D 512
#define NTHREADS 128            // 4 warps = 2 batch rows per block
#define T_SKIP 220.0f
#define T_INT (220 * 1024)
#define ROW_BYTES (KB_D * 4)    // 2048; idx*2048 fits in 32 bits (V=50000)

__device__ __forceinline__ float warp_sum(float v) {
#pragma unroll
    for (int off = 16; off; off >>= 1)
        v += __shfl_xor_sync(0xffffffffu, v, off);
    return v;
}

__device__ __forceinline__ float quarter_d2(float4 r, float4 c) {
    float dx = r.x - c.x, dy = r.y - c.y, dz = r.z - c.z, dw = r.w - c.w;
    float d = dx * dx;
    d = fmaf(dy, dy, d);
    d = fmaf(dz, dz, d);
    d = fmaf(dw, dw, d);
    return d;
}

__device__ __forceinline__ int bound_int(float p) {
    return __float2int_rd(fminf(p, 60000.f) * 1024.f);   // floor -> lower bound
}

// Cold path: warp-uniform entry, ~0.3% of rows. Exact full fp32 distance from
// L1-hot data, then exp + accumulate. 256-element REDUX bound prunes first.
// Lazily zeroes this warp's acc slice on first actual accumulation.
__device__ __noinline__ float slow_path(const float4* __restrict__ rowp,
                                        const float4* __restrict__ cenp,
                                        int lane,
                                        float4* __restrict__ sacc,
                                        int* __restrict__ flag)
{
    const float4 cen0 = __ldg(&cenp[lane]);
    const float4 cen1 = __ldg(&cenp[lane + 32]);
    const float4 r0   = __ldg(&rowp[lane]);
    const float4 r1   = __ldg(&rowp[lane + 32]);
    const float pa  = quarter_d2(r0, cen0) + quarter_d2(r1, cen1);
    const int s2 = __reduce_add_sync(0xffffffffu, bound_int(pa));
    if (s2 > T_INT) return 0.f;                    // provably w == 0.0f

    // lazy init (warp-uniform path; this warp is the only writer of its slice)
    if (*flag == 0) {
#pragma unroll
        for (int i = 0; i < 4; i++)
            sacc[lane + 32 * i] = make_float4(0.f, 0.f, 0.f, 0.f);
        __syncwarp();
        if (lane == 0) *flag = 1;
    }

    const float4 cen2 = __ldg(&cenp[lane + 64]);
    const float4 cen3 = __ldg(&cenp[lane + 96]);
    const float4 r2   = __ldg(&rowp[lane + 64]);
    const float4 r3   = __ldg(&rowp[lane + 96]);
    const float t  = warp_sum(pa);
    const float d2 = t + warp_sum(quarter_d2(r2, cen2) + quarter_d2(r3, cen3));

    const float e = __expf(-0.5f * d2);

    float4 a;
    a = sacc[lane];
    a.x = fmaf(e, r0.x, a.x); a.y = fmaf(e, r0.y, a.y);
    a.z = fmaf(e, r0.z, a.z); a.w = fmaf(e, r0.w, a.w);
    sacc[lane] = a;
    a = sacc[lane + 32];
    a.x = fmaf(e, r1.x, a.x); a.y = fmaf(e, r1.y, a.y);
    a.z = fmaf(e, r1.z, a.z); a.w = fmaf(e, r1.w, a.w);
    sacc[lane + 32] = a;
    a = sacc[lane + 64];
    a.x = fmaf(e, r2.x, a.x); a.y = fmaf(e, r2.y, a.y);
    a.z = fmaf(e, r2.z, a.z); a.w = fmaf(e, r2.w, a.w);
    sacc[lane + 64] = a;
    a = sacc[lane + 96];
    a.x = fmaf(e, r3.x, a.x); a.y = fmaf(e, r3.y, a.y);
    a.z = fmaf(e, r3.z, a.z); a.w = fmaf(e, r3.w, a.w);
    sacc[lane + 96] = a;
    return e;
}

__global__ __launch_bounds__(NTHREADS, 8)
void kre_kernel(const int* __restrict__ context,
                const int* __restrict__ center,
                const float* __restrict__ W,
                float* __restrict__ out)
{
    const int tid  = threadIdx.x;
    const int lane = tid & 31;
    const int wid  = tid >> 5;
    const int b    = blockIdx.x * 2 + (wid >> 1);  // 2 warps per batch row
    const int half = wid & 1;                      // which 16 context rows
    const int fp   = lane & 7;                     // float4 slot within group
    const int grp  = lane >> 3;                    // group = row-within-quad

    __shared__ float4 s_acc[4][KB_D / 4];          // per-warp slices (8 KB)
    __shared__ float  s_esum[4];
    __shared__ int    s_flag[4];
    float4* sacc = s_acc[wid];
    if (lane == 0) s_flag[wid] = 0;

    const int cen_idx = __ldg(&center[b]);
    const char* Wb   = reinterpret_cast<const char*>(W);
    const char* cenb = Wb + (unsigned)cen_idx * ROW_BYTES;
    const float4* cenp = reinterpret_cast<const float4*>(cenb);

    // center elems for this lane's pattern: float4 at fp+8j (j=0..4) = elems 0..159
    float4 cen[5];
#pragma unroll
    for (int j = 0; j < 5; j++) cen[j] = __ldg(&cenp[fp + 8 * j]);

    const int* ctxp = context + b * KB_C + half * 16;
    float esum = 0.f;

    // ---- 4 quads x 4 rows: group-parallel 160-element bound ----
    unsigned m[4];
#pragma unroll
    for (int q = 0; q < 4; q++) {
        const int idx = __ldg(&ctxp[4 * q + grp]);           // row for my group
        const float4* rowp =
            reinterpret_cast<const float4*>(Wb + (unsigned)idx * ROW_BYTES);

        float4 r0 = __ldg(&rowp[fp]);
        float4 r1 = __ldg(&rowp[fp + 8]);
        float4 r2 = __ldg(&rowp[fp + 16]);
        float4 r3 = __ldg(&rowp[fp + 24]);
        float4 r4 = __ldg(&rowp[fp + 32]);

        float p0 = quarter_d2(r0, cen[0]);
        float p1 = quarter_d2(r1, cen[1]);
        float p2 = quarter_d2(r2, cen[2]);
        float p3 = quarter_d2(r3, cen[3]);
        float p4 = quarter_d2(r4, cen[4]);
        float p  = ((p0 + p1) + (p2 + p3)) + p4;             // 20-elem lane partial

        // 3-level tree within each 8-lane group: all 4 rows reduced at once
        p += __shfl_xor_sync(0xffffffffu, p, 4);
        p += __shfl_xor_sync(0xffffffffu, p, 2);
        p += __shfl_xor_sync(0xffffffffu, p, 1);

        m[q] = __ballot_sync(0xffffffffu, p <= T_SKIP);      // warp-uniform mask
    }

    if ((m[0] | m[1] | m[2] | m[3]) != 0) {        // rare (~5% of warps)
#pragma unroll
        for (int q = 0; q < 4; q++) {
#pragma unroll
            for (int g = 0; g < 4; g++) {
                if ((m[q] >> (8 * g)) & 1u) {
                    const int idx = __ldg(&ctxp[4 * q + g]);
                    const float4* rowp = reinterpret_cast<const float4*>(
                        Wb + (unsigned)idx * ROW_BYTES);
                    esum += slow_path(rowp, cenp, lane, sacc, &s_flag[wid]);
                }
            }
        }
    }

    if (lane == 0) s_esum[wid] = esum;
    __syncthreads();

    // pair combine: warps {0,1} -> b0, warps {2,3} -> b1; 64 lanes per pair
    const int pair  = tid >> 6;
    const int ptid  = tid & 63;
    const int b_out = blockIdx.x * 2 + pair;
    const int f0 = s_flag[pair * 2];
    const int f1 = s_flag[pair * 2 + 1];

    float4* op = reinterpret_cast<float4*>(out + (size_t)b_out * KB_D);

    if ((f0 | f1) == 0) {
        // common case (~90% of pairs): no survivors -> output exactly 0
        const float4 z = make_float4(0.f, 0.f, 0.f, 0.f);
#pragma unroll
        for (int i = 0; i < 2; i++)
            __stcs(&op[ptid + 64 * i], z);
    } else {
        const float inv = 1.0f / (s_esum[pair * 2] + s_esum[pair * 2 + 1] + 1e-8f);
#pragma unroll
        for (int i = 0; i < 2; i++) {
            const int j = ptid + 64 * i;
            float4 v = make_float4(0.f, 0.f, 0.f, 0.f);
            if (f0) {
                const float4 a0 = s_acc[pair * 2][j];
                v.x += a0.x; v.y += a0.y; v.z += a0.z; v.w += a0.w;
            }
            if (f1) {
                const float4 a1 = s_acc[pair * 2 + 1][j];
                v.x += a1.x; v.y += a1.y; v.z += a1.z; v.w += a1.w;
            }
            v.x *= inv; v.y *= inv; v.z *= inv; v.w *= inv;
            __stcs(&op[j], v);
        }
    }
}

extern "C" void kernel_launch(void* const* d_in, const int* in_sizes, int n_in,
                              void* d_out, int out_size)
{
    const int* context = (const int*)d_in[0];
    const int* center  = (const int*)d_in[1];
    const float* W     = (const float*)d_in[2];
    for (int i = 0; i < n_in; i++) {
        if (in_sizes[i] == KB_B * KB_C)      context = (const int*)d_in[i];
        else if (in_sizes[i] == KB_B)        center  = (const int*)d_in[i];
        else if (in_sizes[i] > KB_B * KB_C)  W       = (const float*)d_in[i];
    }
    float* out = (float*)d_out;
    kre_kernel<<<KB_B / 2, NTHREADS>>>(context, center, W, out);
}